// round 5
// baseline (speedup 1.0000x reference)
#include <cuda_runtime.h>

// SidedDistance: for each point in S1 (B,N,3), index of nearest point in S2 (B,M,3).
// B=4, N=M=8192.
// OUTPUT CONTRACT: pipeline dtypes are {float32, int32, bf16}; reference's int64 argmin
// is coerced -> we write indices as FLOAT32 (exact for idx < 2^24).
//
// Arithmetic reproduces the reference lowering exactly (ties must order identically):
//   cross = fma(z,sz, fma(y,sy, fl(x*sx)))   (K=3 dot, ascending-k FMA from 0:
//                                             matches cuBLAS sgemm / Eigen-FMA)
//   n     = fl(fl(x^2)+fl(y^2)) + fl(z^2)    (mul + tree of adds, no contraction)
//   d2    = fl(fl(n1 - fl(2*cross)) + n2)
//   argmin: ascending scan, strict <  => first index (np.argmin semantics)

#define NBATCH   4
#define NQ       8192
#define M        8192
#define THREADS  256                 // 1 query per thread
#define QB       256                 // queries per block
#define TILE     2048                // candidates per smem tile (32 KB)
#define NTILE    (M / TILE)          // 4
#define BLOCKS_PER_BATCH (NQ / QB)   // 32

__global__ __launch_bounds__(THREADS, 1)
void SidedDistance_kernel(const float* __restrict__ S1,
                          const float* __restrict__ S2,
                          float* __restrict__ out)
{
    __shared__ float4 tile[TILE];    // {sx, sy, sz, n2}

    const int b     = blockIdx.x >> 5;
    const int qc    = blockIdx.x & 31;
    const int qbase = qc * QB;
    const int tid   = threadIdx.x;

    // ---- this thread's query point + n1 (reference rounding) ----
    const float* s1q = S1 + ((size_t)b * NQ + qbase + tid) * 3;
    const float ax = s1q[0], ay = s1q[1], az = s1q[2];
    const float n1 = __fadd_rn(__fadd_rn(__fmul_rn(ax, ax), __fmul_rn(ay, ay)),
                               __fmul_rn(az, az));

    const float* s2b = S2 + (size_t)b * M * 3;

    float best = __int_as_float(0x7f800000);   // +inf
    int   bi   = 0;

    for (int t = 0; t < NTILE; ++t) {
        // ---- stage tile t ----
        for (int j = tid; j < TILE; j += THREADS) {
            const float* q = s2b + 3 * (t * TILE + j);
            float x = q[0], y = q[1], z = q[2];
            float n2 = __fadd_rn(__fadd_rn(__fmul_rn(x, x), __fmul_rn(y, y)),
                                 __fmul_rn(z, z));
            tile[j] = make_float4(x, y, z, n2);
        }
        __syncthreads();

        const int jb = t * TILE;
#pragma unroll 8
        for (int k = 0; k < TILE; ++k) {
            float4 s = tile[k];
            // cross: fma(x,sx,0) == fl(x*sx), then ascending fma chain
            float c  = __fmaf_rn(az, s.z, __fmaf_rn(ay, s.y, __fmul_rn(ax, s.x)));
            // d2 = ((n1 - 2c) + n2), each op rounded once
            float d  = __fadd_rn(__fsub_rn(n1, __fadd_rn(c, c)), s.w);
            if (d < best) { best = d; bi = jb + k; }
        }
        __syncthreads();
    }

    out[(size_t)b * NQ + qbase + tid] = (float)bi;
}

extern "C" void kernel_launch(void* const* d_in, const int* in_sizes, int n_in,
                              void* d_out, int out_size)
{
    const float* S1 = (const float*)d_in[0];
    const float* S2 = (const float*)d_in[1];
    float* out = (float*)d_out;

    SidedDistance_kernel<<<NBATCH * BLOCKS_PER_BATCH, THREADS>>>(S1, S2, out);
}